// round 1
// baseline (speedup 1.0000x reference)
#include <cuda_runtime.h>
#include <cuda_bf16.h>
#include <math.h>

// Problem constants
#define BATCH   2
#define SEQ     2048
#define DMODEL  2048
#define NHEADS  16
#define DHEAD   128
#define M_TOT   (BATCH * SEQ)          // 4096

// Scratch (device globals: allocation-free per harness rules)
__device__ float g_Q[(size_t)BATCH * NHEADS * SEQ * DHEAD];  // [bh][s][d]
__device__ float g_K[(size_t)BATCH * NHEADS * SEQ * DHEAD];
__device__ float g_V[(size_t)BATCH * NHEADS * SEQ * DHEAD];
__device__ float g_Z[(size_t)M_TOT * DMODEL];                // [b*s][h*d]

// ---------------------------------------------------------------------------
// Kernel 1: fused QKV projection.
// Grid: (M_TOT/128, 48).  blockIdx.y: [0,16) Q-head, [16,32) K-head, [32,48) V-head.
// C[128x128] = X[128x2048] * W_head[2048x128] + bias, written to g_{Q,K,V} in
// [b*NHEADS+h][s][d] layout.
// ---------------------------------------------------------------------------
__global__ void __launch_bounds__(256) qkv_kernel(
    const float* __restrict__ X,
    const float* __restrict__ WQ, const float* __restrict__ WK, const float* __restrict__ WV,
    const float* __restrict__ bQ, const float* __restrict__ bK, const float* __restrict__ bV)
{
    const int type = blockIdx.y >> 4;        // 0=Q 1=K 2=V
    const int head = blockIdx.y & 15;

    const float* B    = (type == 0 ? WQ : type == 1 ? WK : WV) + (size_t)head * DMODEL * DHEAD;
    const float* bias = (type == 0 ? bQ : type == 1 ? bK : bV) + head * DHEAD;
    float* Out        = (type == 0 ? g_Q : type == 1 ? g_K : g_V);

    __shared__ float As[8][128];   // A transposed: As[k][m]
    __shared__ float Bs[8][128];   // Bs[k][n]

    const int tid = threadIdx.x;
    const int tx  = tid & 15;      // n-group
    const int ty  = tid >> 4;      // m-group
    const int m0  = blockIdx.x * 128;

    // A tile load mapping: 128 rows x 8 cols -> 256 float4, 1 per thread
    const int a_row  = tid >> 1;
    const int a_col4 = (tid & 1) * 4;
    // B tile load mapping: 8 rows x 128 cols -> 256 float4, 1 per thread
    const int b_row  = tid >> 5;
    const int b_col4 = (tid & 31) * 4;

    const float* Aptr = X + (size_t)(m0 + a_row) * DMODEL + a_col4;
    const float* Bptr = B + (size_t)b_row * DHEAD + b_col4;

    float acc[8][8];
#pragma unroll
    for (int i = 0; i < 8; i++)
#pragma unroll
        for (int j = 0; j < 8; j++) acc[i][j] = 0.f;

    for (int k0 = 0; k0 < DMODEL; k0 += 8) {
        float4 av = *(const float4*)Aptr;  Aptr += 8;
        float4 bv = *(const float4*)Bptr;  Bptr += 8 * DHEAD;
        As[a_col4 + 0][a_row] = av.x;
        As[a_col4 + 1][a_row] = av.y;
        As[a_col4 + 2][a_row] = av.z;
        As[a_col4 + 3][a_row] = av.w;
        *(float4*)&Bs[b_row][b_col4] = bv;
        __syncthreads();
#pragma unroll
        for (int kk = 0; kk < 8; kk++) {
            float4 a0 = *(const float4*)&As[kk][ty * 8];
            float4 a1 = *(const float4*)&As[kk][ty * 8 + 4];
            float4 b0 = *(const float4*)&Bs[kk][tx * 8];
            float4 b1 = *(const float4*)&Bs[kk][tx * 8 + 4];
            float af[8] = {a0.x, a0.y, a0.z, a0.w, a1.x, a1.y, a1.z, a1.w};
            float bf[8] = {b0.x, b0.y, b0.z, b0.w, b1.x, b1.y, b1.z, b1.w};
#pragma unroll
            for (int i = 0; i < 8; i++)
#pragma unroll
                for (int j = 0; j < 8; j++) acc[i][j] += af[i] * bf[j];
        }
        __syncthreads();
    }

#pragma unroll
    for (int i = 0; i < 8; i++) {
        const int m = m0 + ty * 8 + i;
        const int b = m >> 11;               // / SEQ
        const int s = m & 2047;
        float* outrow = Out + (((size_t)(b * NHEADS + head)) * SEQ + s) * DHEAD;
#pragma unroll
        for (int j = 0; j < 8; j += 4) {
            const int n = tx * 8 + j;
            float4 v = make_float4(acc[i][j]   + bias[n],
                                   acc[i][j+1] + bias[n+1],
                                   acc[i][j+2] + bias[n+2],
                                   acc[i][j+3] + bias[n+3]);
            *(float4*)(outrow + n) = v;
        }
    }
}

// ---------------------------------------------------------------------------
// Kernel 2: causal flash attention per (b,h).
// Grid: (SEQ/64 = 32 q-blocks, BATCH*NHEADS = 32).  256 threads (16x16).
// BLOCK_M = BLOCK_N = 64, D = 128, fp32, online softmax.
// smem rows padded to 132 floats (16B/row bank skew) for conflict-free K reads.
// ---------------------------------------------------------------------------
#define BM 64
#define BN 64
#define PAD_ROW 132        // 128 + 4
#define PPAD 68            // 64 + 4
#define ATTN_SMEM ((3 * BM * PAD_ROW + BM * PPAD) * 4)   // 118784 bytes

__global__ void __launch_bounds__(256) attn_kernel()
{
    extern __shared__ float sm[];
    float* Qs = sm;                        // [64][132]
    float* Ks = Qs + BM * PAD_ROW;         // [64][132]
    float* Vs = Ks + BM * PAD_ROW;         // [64][132]
    float* Ps = Vs + BM * PAD_ROW;         // [64][68]

    const int bh = blockIdx.y;             // b*16 + h
    const int qb = blockIdx.x;
    const float* Qbase = g_Q + (size_t)bh * SEQ * DHEAD + (size_t)qb * BM * DHEAD;
    const float* Kbase = g_K + (size_t)bh * SEQ * DHEAD;
    const float* Vbase = g_V + (size_t)bh * SEQ * DHEAD;

    const int tid = threadIdx.x;
    const int tx  = tid & 15;
    const int ty  = tid >> 4;

    // Load Q tile (64x128) into padded smem
    for (int i = tid; i < BM * 32; i += 256) {          // 2048 float4
        const int row = i >> 5;
        const int c4  = (i & 31) << 2;
        *(float4*)&Qs[row * PAD_ROW + c4] = *(const float4*)(Qbase + (row << 7) + c4);
    }

    float m_i[4], l_i[4];
    float o[4][8];
#pragma unroll
    for (int i = 0; i < 4; i++) {
        m_i[i] = -3.0e38f; l_i[i] = 0.f;
#pragma unroll
        for (int j = 0; j < 8; j++) o[i][j] = 0.f;
    }

    const float scale = 0.08838834764831845f;   // 1/sqrt(128)
    const int nblocks = qb + 1;                 // causal

    for (int kb = 0; kb < nblocks; kb++) {
        // Load K and V tiles
        for (int i = tid; i < BM * 32; i += 256) {
            const int row = i >> 5;
            const int c4  = (i & 31) << 2;
            const int goff = ((kb * BM + row) << 7) + c4;
            *(float4*)&Ks[row * PAD_ROW + c4] = *(const float4*)(Kbase + goff);
            *(float4*)&Vs[row * PAD_ROW + c4] = *(const float4*)(Vbase + goff);
        }
        __syncthreads();

        // S tile: thread owns rows ty*4+i (queries), keys j*16+tx
        float s[4][4];
#pragma unroll
        for (int i = 0; i < 4; i++)
#pragma unroll
            for (int j = 0; j < 4; j++) s[i][j] = 0.f;

#pragma unroll 4
        for (int d = 0; d < DHEAD; d += 4) {
            float4 q0 = *(const float4*)&Qs[(ty * 4 + 0) * PAD_ROW + d];
            float4 q1 = *(const float4*)&Qs[(ty * 4 + 1) * PAD_ROW + d];
            float4 q2 = *(const float4*)&Qs[(ty * 4 + 2) * PAD_ROW + d];
            float4 q3 = *(const float4*)&Qs[(ty * 4 + 3) * PAD_ROW + d];
            float4 k0 = *(const float4*)&Ks[(tx +  0) * PAD_ROW + d];
            float4 k1 = *(const float4*)&Ks[(tx + 16) * PAD_ROW + d];
            float4 k2 = *(const float4*)&Ks[(tx + 32) * PAD_ROW + d];
            float4 k3 = *(const float4*)&Ks[(tx + 48) * PAD_ROW + d];
            float4 qv[4] = {q0, q1, q2, q3};
            float4 kv[4] = {k0, k1, k2, k3};
#pragma unroll
            for (int i = 0; i < 4; i++)
#pragma unroll
                for (int j = 0; j < 4; j++) {
                    s[i][j] += qv[i].x * kv[j].x;
                    s[i][j] += qv[i].y * kv[j].y;
                    s[i][j] += qv[i].z * kv[j].z;
                    s[i][j] += qv[i].w * kv[j].w;
                }
        }

        // Scale + causal mask + online softmax
        float mnew[4], fac[4];
#pragma unroll
        for (int i = 0; i < 4; i++) {
            const int qi = qb * BM + ty * 4 + i;
            float mrow = -3.0e38f;
#pragma unroll
            for (int j = 0; j < 4; j++) {
                const int kg = kb * BM + j * 16 + tx;
                s[i][j] = (kg > qi) ? -3.0e38f : s[i][j] * scale;
                mrow = fmaxf(mrow, s[i][j]);
            }
#pragma unroll
            for (int off = 8; off; off >>= 1)
                mrow = fmaxf(mrow, __shfl_xor_sync(0xffffffffu, mrow, off));
            mnew[i] = fmaxf(m_i[i], mrow);
            fac[i]  = __expf(m_i[i] - mnew[i]);   // 0 on first block
            float lrow = 0.f;
#pragma unroll
            for (int j = 0; j < 4; j++) {
                float p = __expf(s[i][j] - mnew[i]);  // exact 0 when masked
                s[i][j] = p;
                lrow += p;
            }
#pragma unroll
            for (int off = 8; off; off >>= 1)
                lrow += __shfl_xor_sync(0xffffffffu, lrow, off);
            l_i[i] = l_i[i] * fac[i] + lrow;
            m_i[i] = mnew[i];
#pragma unroll
            for (int j = 0; j < 8; j++) o[i][j] *= fac[i];
            // stash P
#pragma unroll
            for (int j = 0; j < 4; j++)
                Ps[(ty * 4 + i) * PPAD + j * 16 + tx] = s[i][j];
        }
        __syncthreads();

        // O += P @ V  (thread owns rows ty*4+i, cols tx*8..tx*8+7)
#pragma unroll 4
        for (int k = 0; k < BN; k++) {
            float4 v0 = *(const float4*)&Vs[k * PAD_ROW + tx * 8];
            float4 v1 = *(const float4*)&Vs[k * PAD_ROW + tx * 8 + 4];
            float pr[4];
#pragma unroll
            for (int i = 0; i < 4; i++) pr[i] = Ps[(ty * 4 + i) * PPAD + k];
#pragma unroll
            for (int i = 0; i < 4; i++) {
                o[i][0] += pr[i] * v0.x;  o[i][1] += pr[i] * v0.y;
                o[i][2] += pr[i] * v0.z;  o[i][3] += pr[i] * v0.w;
                o[i][4] += pr[i] * v1.x;  o[i][5] += pr[i] * v1.y;
                o[i][6] += pr[i] * v1.z;  o[i][7] += pr[i] * v1.w;
            }
        }
        __syncthreads();
    }

    // Normalize and write to g_Z[b*SEQ+s][h*DHEAD+d]
    const int b    = bh >> 4;
    const int head = bh & 15;
#pragma unroll
    for (int i = 0; i < 4; i++) {
        const float inv_l = 1.f / l_i[i];
        const int srow = qb * BM + ty * 4 + i;
        float* zrow = g_Z + ((size_t)(b * SEQ + srow)) * DMODEL + head * DHEAD + tx * 8;
        float4 z0 = make_float4(o[i][0]*inv_l, o[i][1]*inv_l, o[i][2]*inv_l, o[i][3]*inv_l);
        float4 z1 = make_float4(o[i][4]*inv_l, o[i][5]*inv_l, o[i][6]*inv_l, o[i][7]*inv_l);
        *(float4*)zrow = z0;
        *(float4*)(zrow + 4) = z1;
    }
}

// ---------------------------------------------------------------------------
// Kernel 3: output projection.  out[4096x2048] = Z[4096x2048] @ WO[2048x2048] + bO
// Grid: (32, 16), same 128x128x8 SGEMM structure.
// ---------------------------------------------------------------------------
__global__ void __launch_bounds__(256) proj_kernel(
    const float* __restrict__ WO, const float* __restrict__ bO, float* __restrict__ out)
{
    __shared__ float As[8][128];
    __shared__ float Bs[8][128];

    const int tid = threadIdx.x;
    const int tx  = tid & 15;
    const int ty  = tid >> 4;
    const int m0  = blockIdx.x * 128;
    const int n0  = blockIdx.y * 128;

    const int a_row  = tid >> 1;
    const int a_col4 = (tid & 1) * 4;
    const int b_row  = tid >> 5;
    const int b_col4 = (tid & 31) * 4;

    const float* Aptr = g_Z + (size_t)(m0 + a_row) * DMODEL + a_col4;
    const float* Bptr = WO  + (size_t)b_row * DMODEL + n0 + b_col4;

    float acc[8][8];
#pragma unroll
    for (int i = 0; i < 8; i++)
#pragma unroll
        for (int j = 0; j < 8; j++) acc[i][j] = 0.f;

    for (int k0 = 0; k0 < DMODEL; k0 += 8) {
        float4 av = *(const float4*)Aptr;  Aptr += 8;
        float4 bv = *(const float4*)Bptr;  Bptr += 8 * DMODEL;
        As[a_col4 + 0][a_row] = av.x;
        As[a_col4 + 1][a_row] = av.y;
        As[a_col4 + 2][a_row] = av.z;
        As[a_col4 + 3][a_row] = av.w;
        *(float4*)&Bs[b_row][b_col4] = bv;
        __syncthreads();
#pragma unroll
        for (int kk = 0; kk < 8; kk++) {
            float4 a0 = *(const float4*)&As[kk][ty * 8];
            float4 a1 = *(const float4*)&As[kk][ty * 8 + 4];
            float4 b0 = *(const float4*)&Bs[kk][tx * 8];
            float4 b1 = *(const float4*)&Bs[kk][tx * 8 + 4];
            float af[8] = {a0.x, a0.y, a0.z, a0.w, a1.x, a1.y, a1.z, a1.w};
            float bf[8] = {b0.x, b0.y, b0.z, b0.w, b1.x, b1.y, b1.z, b1.w};
#pragma unroll
            for (int i = 0; i < 8; i++)
#pragma unroll
                for (int j = 0; j < 8; j++) acc[i][j] += af[i] * bf[j];
        }
        __syncthreads();
    }

#pragma unroll
    for (int i = 0; i < 8; i++) {
        const int m = m0 + ty * 8 + i;
        float* outrow = out + (size_t)m * DMODEL + n0;
#pragma unroll
        for (int j = 0; j < 8; j += 4) {
            const int n = tx * 8 + j;
            float4 v = make_float4(acc[i][j]   + bO[n0 + n],
                                   acc[i][j+1] + bO[n0 + n + 1],
                                   acc[i][j+2] + bO[n0 + n + 2],
                                   acc[i][j+3] + bO[n0 + n + 3]);
            *(float4*)(outrow + n) = v;
        }
    }
}

// ---------------------------------------------------------------------------
extern "C" void kernel_launch(void* const* d_in, const int* in_sizes, int n_in,
                              void* d_out, int out_size)
{
    const float* X  = (const float*)d_in[0];
    const float* WQ = (const float*)d_in[1];
    const float* bQ = (const float*)d_in[2];
    const float* WK = (const float*)d_in[3];
    const float* bK = (const float*)d_in[4];
    const float* WV = (const float*)d_in[5];
    const float* bV = (const float*)d_in[6];
    const float* WO = (const float*)d_in[7];
    const float* bO = (const float*)d_in[8];
    float* out = (float*)d_out;

    cudaFuncSetAttribute(attn_kernel, cudaFuncAttributeMaxDynamicSharedMemorySize, ATTN_SMEM);

    qkv_kernel<<<dim3(M_TOT / 128, 48), 256>>>(X, WQ, WK, WV, bQ, bK, bV);
    attn_kernel<<<dim3(SEQ / BM, BATCH * NHEADS), 256, ATTN_SMEM>>>();
    proj_kernel<<<dim3(M_TOT / 128, DMODEL / 128), 256>>>(WO, bO, out);
}

// round 3
// speedup vs baseline: 1.9167x; 1.9167x over previous
#include <cuda_runtime.h>
#include <cuda_bf16.h>
#include <cstdint>
#include <math.h>

// Problem constants
#define BATCH   2
#define SEQ     2048
#define DMODEL  2048
#define NHEADS  16
#define DHEAD   128
#define M_TOT   (BATCH * SEQ)          // 4096

// Scratch (device globals: allocation-free per harness rules)
__device__ float g_Q[(size_t)BATCH * NHEADS * SEQ * DHEAD];
__device__ float g_K[(size_t)BATCH * NHEADS * SEQ * DHEAD];
__device__ float g_V[(size_t)BATCH * NHEADS * SEQ * DHEAD];
__device__ float g_Z[(size_t)M_TOT * DMODEL];
__device__ float g_WT[(size_t)48 * DHEAD * DMODEL];    // transposed QKV weights [mat][n][k]
__device__ float g_WOT[(size_t)DMODEL * DMODEL];       // transposed W_O [n][k]

__device__ __forceinline__ float to_tf32(float x) {
    float r;
    asm("cvt.rna.tf32.f32 %0, %1;" : "=f"(r) : "f"(x));
    return r;
}

// m16n8k8 tf32 MMA, D = A*B + D (fp32 accumulate)
__device__ __forceinline__ void mma_m16n8k8_tf32(
    float* d, const uint32_t* a, const uint32_t* b)
{
    asm volatile(
        "mma.sync.aligned.m16n8k8.row.col.f32.tf32.tf32.f32 "
        "{%0,%1,%2,%3}, {%4,%5,%6,%7}, {%8,%9}, {%0,%1,%2,%3};"
        : "+f"(d[0]), "+f"(d[1]), "+f"(d[2]), "+f"(d[3])
        : "r"(a[0]), "r"(a[1]), "r"(a[2]), "r"(a[3]), "r"(b[0]), "r"(b[1]));
}

// ---------------------------------------------------------------------------
// Shared mma.sync tf32 mainloop.
// C[128x128] = A[128x2048] (row-major, ld=2048) @ BT[128x2048]^T (BT is [n][k]).
// 256 threads = 8 warps (2x4); warp tile 64x32; K-chunk 32, double-buffered.
// Smem rows padded to 36 floats (fragment loads provably conflict-free).
// ---------------------------------------------------------------------------
#define TILE_F   (128 * 36)                 // floats per (A or B) buffer
#define GEMM_SMEM (4 * TILE_F * 4)          // 2 bufs x (A+B) x 4B = 73728
#define NCHUNK_MM (DMODEL / 32)             // 64

__device__ __forceinline__ void gemm_mainloop_mma(
    const float* __restrict__ A, const float* __restrict__ BT,
    float* smem, float acc[4][4][4])
{
    const int tid  = threadIdx.x;
    const int wid  = tid >> 5, lane = tid & 31;
    const int wm   = (wid >> 2) * 64;       // warp m-offset (0 or 64)
    const int wn   = (wid & 3) * 32;        // warp n-offset
    const int g    = lane >> 2;             // group id 0..7
    const int tg   = lane & 3;              // thread-in-group
    const int lrow = tid >> 3;              // 0..31
    const int lc4  = (tid & 7) * 4;         // float4 col within K-chunk

    float* As = smem;                       // [2][128*36]
    float* Bs = smem + 2 * TILE_F;          // [2][128*36]

#pragma unroll
    for (int fm = 0; fm < 4; fm++)
#pragma unroll
        for (int fn = 0; fn < 4; fn++)
#pragma unroll
            for (int i = 0; i < 4; i++) acc[fm][fn][i] = 0.f;

    float4 pa[4], pb[4];

#define GLOAD(c) do {                                                           \
    _Pragma("unroll")                                                           \
    for (int p = 0; p < 4; p++) {                                               \
        pa[p] = *(const float4*)(A  + (size_t)(lrow + 32 * p) * DMODEL + (c) * 32 + lc4); \
        pb[p] = *(const float4*)(BT + (size_t)(lrow + 32 * p) * DMODEL + (c) * 32 + lc4); \
    }                                                                           \
} while (0)

#define SSTORE(buf) do {                                                        \
    _Pragma("unroll")                                                           \
    for (int p = 0; p < 4; p++) {                                               \
        float4 va = pa[p], vb = pb[p];                                          \
        va.x = to_tf32(va.x); va.y = to_tf32(va.y);                             \
        va.z = to_tf32(va.z); va.w = to_tf32(va.w);                             \
        vb.x = to_tf32(vb.x); vb.y = to_tf32(vb.y);                             \
        vb.z = to_tf32(vb.z); vb.w = to_tf32(vb.w);                             \
        *(float4*)&As[(buf) * TILE_F + (lrow + 32 * p) * 36 + lc4] = va;        \
        *(float4*)&Bs[(buf) * TILE_F + (lrow + 32 * p) * 36 + lc4] = vb;        \
    }                                                                           \
} while (0)

    GLOAD(0);
    SSTORE(0);
    __syncthreads();

    for (int c = 0; c < NCHUNK_MM; c++) {
        const int b = c & 1;
        if (c + 1 < NCHUNK_MM) GLOAD(c + 1);

        const float* as = As + b * TILE_F;
        const float* bs = Bs + b * TILE_F;
#pragma unroll
        for (int kk = 0; kk < 4; kk++) {
            uint32_t af[4][4], bf[4][2];
#pragma unroll
            for (int fm = 0; fm < 4; fm++) {
                const int m = wm + fm * 16 + g;
                af[fm][0] = __float_as_uint(as[m * 36 + kk * 8 + tg]);
                af[fm][1] = __float_as_uint(as[(m + 8) * 36 + kk * 8 + tg]);
                af[fm][2] = __float_as_uint(as[m * 36 + kk * 8 + tg + 4]);
                af[fm][3] = __float_as_uint(as[(m + 8) * 36 + kk * 8 + tg + 4]);
            }
#pragma unroll
            for (int fn = 0; fn < 4; fn++) {
                const int n = wn + fn * 8 + g;
                bf[fn][0] = __float_as_uint(bs[n * 36 + kk * 8 + tg]);
                bf[fn][1] = __float_as_uint(bs[n * 36 + kk * 8 + tg + 4]);
            }
#pragma unroll
            for (int fm = 0; fm < 4; fm++)
#pragma unroll
                for (int fn = 0; fn < 4; fn++)
                    mma_m16n8k8_tf32(acc[fm][fn], af[fm], bf[fn]);
        }

        if (c + 1 < NCHUNK_MM) SSTORE((c + 1) & 1);
        __syncthreads();
    }
#undef GLOAD
#undef SSTORE
}

// ---------------------------------------------------------------------------
// Kernel 1: QKV projection via mma.sync.  Grid (32, 48).
// ---------------------------------------------------------------------------
__global__ void __launch_bounds__(256, 1) qkv_gemm(
    const float* __restrict__ X,
    const float* __restrict__ bQ, const float* __restrict__ bK, const float* __restrict__ bV)
{
    extern __shared__ float smem[];
    const int mat  = blockIdx.y;
    const int type = mat >> 4;
    const int head = mat & 15;
    const int m0   = blockIdx.x * 128;

    const float* A  = X + (size_t)m0 * DMODEL;
    const float* BT = g_WT + (size_t)mat * DHEAD * DMODEL;

    float acc[4][4][4];
    gemm_mainloop_mma(A, BT, smem, acc);

    const float* bias = (type == 0 ? bQ : type == 1 ? bK : bV) + head * DHEAD;
    float* Out = (type == 0 ? g_Q : type == 1 ? g_K : g_V);

    const int tid  = threadIdx.x;
    const int wid  = tid >> 5, lane = tid & 31;
    const int wm   = (wid >> 2) * 64;
    const int wn   = (wid & 3) * 32;
    const int g    = lane >> 2;
    const int tg   = lane & 3;

#pragma unroll
    for (int fm = 0; fm < 4; fm++) {
#pragma unroll
        for (int half = 0; half < 2; half++) {
            const int m = m0 + wm + fm * 16 + g + half * 8;
            const int bb = m >> 11;
            const int s  = m & 2047;
            float* orow = Out + (((size_t)(bb * NHEADS + head)) * SEQ + s) * DHEAD;
#pragma unroll
            for (int fn = 0; fn < 4; fn++) {
                const int col = wn + fn * 8 + 2 * tg;
                float2 v;
                v.x = acc[fm][fn][2 * half]     + bias[col];
                v.y = acc[fm][fn][2 * half + 1] + bias[col + 1];
                *(float2*)(orow + col) = v;
            }
        }
    }
}

// ---------------------------------------------------------------------------
// Kernel 3: output projection via mma.sync.  Grid (32, 16).
// ---------------------------------------------------------------------------
__global__ void __launch_bounds__(256, 1) proj_gemm(
    const float* __restrict__ bO, float* __restrict__ out)
{
    extern __shared__ float smem[];
    const int m0 = blockIdx.x * 128;
    const int n0 = blockIdx.y * 128;

    const float* A  = g_Z + (size_t)m0 * DMODEL;
    const float* BT = g_WOT + (size_t)n0 * DMODEL;

    float acc[4][4][4];
    gemm_mainloop_mma(A, BT, smem, acc);

    const int tid  = threadIdx.x;
    const int wid  = tid >> 5, lane = tid & 31;
    const int wm   = (wid >> 2) * 64;
    const int wn   = (wid & 3) * 32;
    const int g    = lane >> 2;
    const int tg   = lane & 3;

#pragma unroll
    for (int fm = 0; fm < 4; fm++) {
#pragma unroll
        for (int half = 0; half < 2; half++) {
            const int m = m0 + wm + fm * 16 + g + half * 8;
            float* orow = out + (size_t)m * DMODEL + n0;
#pragma unroll
            for (int fn = 0; fn < 4; fn++) {
                const int col = wn + fn * 8 + 2 * tg;
                float2 v;
                v.x = acc[fm][fn][2 * half]     + bO[n0 + col];
                v.y = acc[fm][fn][2 * half + 1] + bO[n0 + col + 1];
                *(float2*)(orow + col) = v;
            }
        }
    }
}

// ---------------------------------------------------------------------------
// Batched transpose: in [z][R][C] -> out [z][C][R]
// ---------------------------------------------------------------------------
__global__ void __launch_bounds__(256) transpose_w(
    const float* __restrict__ in, float* __restrict__ out, int R, int C)
{
    __shared__ float t[32][33];
    const size_t zo = (size_t)blockIdx.z * R * C;
    in  += zo;
    out += zo;
    const int r0 = blockIdx.x * 32, c0 = blockIdx.y * 32;
#pragma unroll
    for (int i = threadIdx.y; i < 32; i += 8)
        t[i][threadIdx.x] = in[(size_t)(r0 + i) * C + c0 + threadIdx.x];
    __syncthreads();
#pragma unroll
    for (int i = threadIdx.y; i < 32; i += 8)
        out[(size_t)(c0 + i) * R + r0 + threadIdx.x] = t[threadIdx.x][i];
}

// ---------------------------------------------------------------------------
// Kernel 2: causal flash attention (fp32, unchanged from R1)
// ---------------------------------------------------------------------------
#define BM 64
#define BN 64
#define PAD_ROW 132
#define PPAD 68
#define ATTN_SMEM ((3 * BM * PAD_ROW + BM * PPAD) * 4)

__global__ void __launch_bounds__(256) attn_kernel()
{
    extern __shared__ float sm[];
    float* Qs = sm;
    float* Ks = Qs + BM * PAD_ROW;
    float* Vs = Ks + BM * PAD_ROW;
    float* Ps = Vs + BM * PAD_ROW;

    const int bh = blockIdx.y;
    const int qb = blockIdx.x;
    const float* Qbase = g_Q + (size_t)bh * SEQ * DHEAD + (size_t)qb * BM * DHEAD;
    const float* Kbase = g_K + (size_t)bh * SEQ * DHEAD;
    const float* Vbase = g_V + (size_t)bh * SEQ * DHEAD;

    const int tid = threadIdx.x;
    const int tx  = tid & 15;
    const int ty  = tid >> 4;

    for (int i = tid; i < BM * 32; i += 256) {
        const int row = i >> 5;
        const int c4  = (i & 31) << 2;
        *(float4*)&Qs[row * PAD_ROW + c4] = *(const float4*)(Qbase + (row << 7) + c4);
    }

    float m_i[4], l_i[4];
    float o[4][8];
#pragma unroll
    for (int i = 0; i < 4; i++) {
        m_i[i] = -3.0e38f; l_i[i] = 0.f;
#pragma unroll
        for (int j = 0; j < 8; j++) o[i][j] = 0.f;
    }

    const float scale = 0.08838834764831845f;
    const int nblocks = qb + 1;

    for (int kb = 0; kb < nblocks; kb++) {
        for (int i = tid; i < BM * 32; i += 256) {
            const int row = i >> 5;
            const int c4  = (i & 31) << 2;
            const int goff = ((kb * BM + row) << 7) + c4;
            *(float4*)&Ks[row * PAD_ROW + c4] = *(const float4*)(Kbase + goff);
            *(float4*)&Vs[row * PAD_ROW + c4] = *(const float4*)(Vbase + goff);
        }
        __syncthreads();

        float s[4][4];
#pragma unroll
        for (int i = 0; i < 4; i++)
#pragma unroll
            for (int j = 0; j < 4; j++) s[i][j] = 0.f;

#pragma unroll 4
        for (int d = 0; d < DHEAD; d += 4) {
            float4 q0 = *(const float4*)&Qs[(ty * 4 + 0) * PAD_ROW + d];
            float4 q1 = *(const float4*)&Qs[(ty * 4 + 1) * PAD_ROW + d];
            float4 q2 = *(const float4*)&Qs[(ty * 4 + 2) * PAD_ROW + d];
            float4 q3 = *(const float4*)&Qs[(ty * 4 + 3) * PAD_ROW + d];
            float4 k0 = *(const float4*)&Ks[(tx +  0) * PAD_ROW + d];
            float4 k1 = *(const float4*)&Ks[(tx + 16) * PAD_ROW + d];
            float4 k2 = *(const float4*)&Ks[(tx + 32) * PAD_ROW + d];
            float4 k3 = *(const float4*)&Ks[(tx + 48) * PAD_ROW + d];
            float4 qv[4] = {q0, q1, q2, q3};
            float4 kv[4] = {k0, k1, k2, k3};
#pragma unroll
            for (int i = 0; i < 4; i++)
#pragma unroll
                for (int j = 0; j < 4; j++) {
                    s[i][j] += qv[i].x * kv[j].x;
                    s[i][j] += qv[i].y * kv[j].y;
                    s[i][j] += qv[i].z * kv[j].z;
                    s[i][j] += qv[i].w * kv[j].w;
                }
        }

        float mnew[4], fac[4];
#pragma unroll
        for (int i = 0; i < 4; i++) {
            const int qi = qb * BM + ty * 4 + i;
            float mrow = -3.0e38f;
#pragma unroll
            for (int j = 0; j < 4; j++) {
                const int kg = kb * BM + j * 16 + tx;
                s[i][j] = (kg > qi) ? -3.0e38f : s[i][j] * scale;
                mrow = fmaxf(mrow, s[i][j]);
            }
#pragma unroll
            for (int off = 8; off; off >>= 1)
                mrow = fmaxf(mrow, __shfl_xor_sync(0xffffffffu, mrow, off));
            mnew[i] = fmaxf(m_i[i], mrow);
            fac[i]  = __expf(m_i[i] - mnew[i]);
            float lrow = 0.f;
#pragma unroll
            for (int j = 0; j < 4; j++) {
                float p = __expf(s[i][j] - mnew[i]);
                s[i][j] = p;
                lrow += p;
            }
#pragma unroll
            for (int off = 8; off; off >>= 1)
                lrow += __shfl_xor_sync(0xffffffffu, lrow, off);
            l_i[i] = l_i[i] * fac[i] + lrow;
            m_i[i] = mnew[i];
#pragma unroll
            for (int j = 0; j < 8; j++) o[i][j] *= fac[i];
#pragma unroll
            for (int j = 0; j < 4; j++)
                Ps[(ty * 4 + i) * PPAD + j * 16 + tx] = s[i][j];
        }
        __syncthreads();

#pragma unroll 4
        for (int k = 0; k < BN; k++) {
            float4 v0 = *(const float4*)&Vs[k * PAD_ROW + tx * 8];
            float4 v1 = *(const float4*)&Vs[k * PAD_ROW + tx * 8 + 4];
            float pr[4];
#pragma unroll
            for (int i = 0; i < 4; i++) pr[i] = Ps[(ty * 4 + i) * PPAD + k];
#pragma unroll
            for (int i = 0; i < 4; i++) {
                o[i][0] += pr[i] * v0.x;  o[i][1] += pr[i] * v0.y;
                o[i][2] += pr[i] * v0.z;  o[i][3] += pr[i] * v0.w;
                o[i][4] += pr[i] * v1.x;  o[i][5] += pr[i] * v1.y;
                o[i][6] += pr[i] * v1.z;  o[i][7] += pr[i] * v1.w;
            }
        }
        __syncthreads();
    }

    const int b    = bh >> 4;
    const int head = bh & 15;
#pragma unroll
    for (int i = 0; i < 4; i++) {
        const float inv_l = 1.f / l_i[i];
        const int srow = qb * BM + ty * 4 + i;
        float* zrow = g_Z + ((size_t)(b * SEQ + srow)) * DMODEL + head * DHEAD + tx * 8;
        float4 z0 = make_float4(o[i][0]*inv_l, o[i][1]*inv_l, o[i][2]*inv_l, o[i][3]*inv_l);
        float4 z1 = make_float4(o[i][4]*inv_l, o[i][5]*inv_l, o[i][6]*inv_l, o[i][7]*inv_l);
        *(float4*)zrow = z0;
        *(float4*)(zrow + 4) = z1;
    }
}

// ---------------------------------------------------------------------------
extern "C" void kernel_launch(void* const* d_in, const int* in_sizes, int n_in,
                              void* d_out, int out_size)
{
    const float* X  = (const float*)d_in[0];
    const float* WQ = (const float*)d_in[1];
    const float* bQ = (const float*)d_in[2];
    const float* WK = (const float*)d_in[3];
    const float* bK = (const float*)d_in[4];
    const float* WV = (const float*)d_in[5];
    const float* bV = (const float*)d_in[6];
    const float* WO = (const float*)d_in[7];
    const float* bO = (const float*)d_in[8];
    float* out = (float*)d_out;

    cudaFuncSetAttribute(qkv_gemm, cudaFuncAttributeMaxDynamicSharedMemorySize, GEMM_SMEM);
    cudaFuncSetAttribute(proj_gemm, cudaFuncAttributeMaxDynamicSharedMemorySize, GEMM_SMEM);
    cudaFuncSetAttribute(attn_kernel, cudaFuncAttributeMaxDynamicSharedMemorySize, ATTN_SMEM);

    float *wt = nullptr, *wot = nullptr;
    cudaGetSymbolAddress((void**)&wt, g_WT);
    cudaGetSymbolAddress((void**)&wot, g_WOT);

    // Transpose weights to [N][K] (K contiguous) for mma.sync "col" operand
    transpose_w<<<dim3(64, 4, 16), dim3(32, 8)>>>(WQ, wt, DMODEL, DHEAD);
    transpose_w<<<dim3(64, 4, 16), dim3(32, 8)>>>(WK, wt + (size_t)16 * DHEAD * DMODEL, DMODEL, DHEAD);
    transpose_w<<<dim3(64, 4, 16), dim3(32, 8)>>>(WV, wt + (size_t)32 * DHEAD * DMODEL, DMODEL, DHEAD);
    transpose_w<<<dim3(64, 64, 1), dim3(32, 8)>>>(WO, wot, DMODEL, DMODEL);

    qkv_gemm<<<dim3(32, 48), 256, GEMM_SMEM>>>(X, bQ, bK, bV);
    attn_kernel<<<dim3(SEQ / BM, BATCH * NHEADS), 256, ATTN_SMEM>>>();
    proj_gemm<<<dim3(32, 16), 256, GEMM_SMEM>>>(bO, out);
}

// round 4
// speedup vs baseline: 3.3377x; 1.7414x over previous
#include <cuda_runtime.h>
#include <cuda_bf16.h>
#include <cstdint>
#include <math.h>

// Problem constants
#define BATCH   2
#define SEQ     2048
#define DMODEL  2048
#define NHEADS  16
#define DHEAD   128
#define M_TOT   (BATCH * SEQ)          // 4096

// Scratch (device globals: allocation-free per harness rules)
__device__ float g_Q[(size_t)BATCH * NHEADS * SEQ * DHEAD];
__device__ float g_K[(size_t)BATCH * NHEADS * SEQ * DHEAD];
__device__ float g_V[(size_t)BATCH * NHEADS * SEQ * DHEAD];
__device__ float g_Z[(size_t)M_TOT * DMODEL];
__device__ float g_WT[(size_t)48 * DHEAD * DMODEL];    // transposed QKV weights [mat][n][k]
__device__ float g_WOT[(size_t)DMODEL * DMODEL];       // transposed W_O [n][k]

// ---------------------------------------------------------------------------
// Helpers
// ---------------------------------------------------------------------------
__device__ __forceinline__ uint32_t f2tf(float x) {
    uint32_t r;
    asm("cvt.rna.tf32.f32 %0, %1;" : "=r"(r) : "f"(x));
    return r;
}
__device__ __forceinline__ uint32_t smem_u32(const void* p) {
    uint32_t a;
    asm("{ .reg .u64 t; cvta.to.shared.u64 t, %1; cvt.u32.u64 %0, t; }" : "=r"(a) : "l"(p));
    return a;
}
__device__ __forceinline__ void mma_m16n8k8_tf32(
    float* d, const uint32_t* a, const uint32_t* b)
{
    asm volatile(
        "mma.sync.aligned.m16n8k8.row.col.f32.tf32.tf32.f32 "
        "{%0,%1,%2,%3}, {%4,%5,%6,%7}, {%8,%9}, {%0,%1,%2,%3};"
        : "+f"(d[0]), "+f"(d[1]), "+f"(d[2]), "+f"(d[3])
        : "r"(a[0]), "r"(a[1]), "r"(a[2]), "r"(a[3]), "r"(b[0]), "r"(b[1]));
}
#define CP_ASYNC16(dst, src) \
    asm volatile("cp.async.cg.shared.global [%0], [%1], 16;" :: "r"(dst), "l"(src))
#define CP_COMMIT  asm volatile("cp.async.commit_group;" ::: "memory")
#define CP_WAIT0   asm volatile("cp.async.wait_group 0;" ::: "memory")
#define CP_WAIT1   asm volatile("cp.async.wait_group 1;" ::: "memory")

// ---------------------------------------------------------------------------
// Shared mma.sync tf32 mainloop with cp.async double buffering.
// C[128x128] = A[128x2048] (row-major) @ BT[128x2048]^T  (BT is [n][k]).
// 256 threads = 8 warps (2x4); warp tile 64x32; K-chunk 32.
// ---------------------------------------------------------------------------
#define TILE_F   (128 * 36)
#define GEMM_SMEM (4 * TILE_F * 4)          // 73728 B
#define NCHUNK_MM (DMODEL / 32)             // 64

__device__ __forceinline__ void gemm_mainloop_mma(
    const float* __restrict__ A, const float* __restrict__ BT,
    float* smem, float acc[4][4][4])
{
    const int tid  = threadIdx.x;
    const int wid  = tid >> 5, lane = tid & 31;
    const int wm   = (wid >> 2) * 64;
    const int wn   = (wid & 3) * 32;
    const int g    = lane >> 2;
    const int tg   = lane & 3;
    const int lrow = tid >> 3;              // 0..31
    const int lc4  = (tid & 7) * 4;

    float* As = smem;
    float* Bs = smem + 2 * TILE_F;
    const uint32_t sA = smem_u32(As);
    const uint32_t sB = smem_u32(Bs);

#pragma unroll
    for (int fm = 0; fm < 4; fm++)
#pragma unroll
        for (int fn = 0; fn < 4; fn++)
#pragma unroll
            for (int i = 0; i < 4; i++) acc[fm][fn][i] = 0.f;

    const float* aBase = A  + (size_t)lrow * DMODEL + lc4;
    const float* bBase = BT + (size_t)lrow * DMODEL + lc4;

#define ISSUE(c, buf) do {                                                      \
    uint32_t _da = sA + (uint32_t)(((buf) * TILE_F + lrow * 36 + lc4) * 4);     \
    uint32_t _db = sB + (uint32_t)(((buf) * TILE_F + lrow * 36 + lc4) * 4);     \
    _Pragma("unroll")                                                           \
    for (int _p = 0; _p < 4; _p++) {                                            \
        CP_ASYNC16(_da + _p * (32 * 36 * 4), aBase + (size_t)_p * 32 * DMODEL + (c) * 32); \
        CP_ASYNC16(_db + _p * (32 * 36 * 4), bBase + (size_t)_p * 32 * DMODEL + (c) * 32); \
    }                                                                           \
    CP_COMMIT;                                                                  \
} while (0)

    ISSUE(0, 0);

    for (int c = 0; c < NCHUNK_MM; c++) {
        if (c + 1 < NCHUNK_MM) { ISSUE(c + 1, (c + 1) & 1); CP_WAIT1; }
        else                   { CP_WAIT0; }
        __syncthreads();

        const float* as = As + (c & 1) * TILE_F;
        const float* bs = Bs + (c & 1) * TILE_F;
#pragma unroll
        for (int kk = 0; kk < 4; kk++) {
            uint32_t af[4][4], bf[4][2];
#pragma unroll
            for (int fm = 0; fm < 4; fm++) {
                const int m = wm + fm * 16 + g;
                af[fm][0] = f2tf(as[m * 36 + kk * 8 + tg]);
                af[fm][1] = f2tf(as[(m + 8) * 36 + kk * 8 + tg]);
                af[fm][2] = f2tf(as[m * 36 + kk * 8 + tg + 4]);
                af[fm][3] = f2tf(as[(m + 8) * 36 + kk * 8 + tg + 4]);
            }
#pragma unroll
            for (int fn = 0; fn < 4; fn++) {
                const int n = wn + fn * 8 + g;
                bf[fn][0] = f2tf(bs[n * 36 + kk * 8 + tg]);
                bf[fn][1] = f2tf(bs[n * 36 + kk * 8 + tg + 4]);
            }
#pragma unroll
            for (int fm = 0; fm < 4; fm++)
#pragma unroll
                for (int fn = 0; fn < 4; fn++)
                    mma_m16n8k8_tf32(acc[fm][fn], af[fm], bf[fn]);
        }
        __syncthreads();
    }
#undef ISSUE
}

// ---------------------------------------------------------------------------
// Kernel 1: QKV projection via mma.sync.  Grid (32, 48).
// ---------------------------------------------------------------------------
__global__ void __launch_bounds__(256, 1) qkv_gemm(
    const float* __restrict__ X,
    const float* __restrict__ bQ, const float* __restrict__ bK, const float* __restrict__ bV)
{
    extern __shared__ float smem[];
    const int mat  = blockIdx.y;
    const int type = mat >> 4;
    const int head = mat & 15;
    const int m0   = blockIdx.x * 128;

    const float* A  = X + (size_t)m0 * DMODEL;
    const float* BT = g_WT + (size_t)mat * DHEAD * DMODEL;

    float acc[4][4][4];
    gemm_mainloop_mma(A, BT, smem, acc);

    const float* bias = (type == 0 ? bQ : type == 1 ? bK : bV) + head * DHEAD;
    float* Out = (type == 0 ? g_Q : type == 1 ? g_K : g_V);

    const int tid  = threadIdx.x;
    const int wid  = tid >> 5, lane = tid & 31;
    const int wm   = (wid >> 2) * 64;
    const int wn   = (wid & 3) * 32;
    const int g    = lane >> 2;
    const int tg   = lane & 3;

#pragma unroll
    for (int fm = 0; fm < 4; fm++) {
#pragma unroll
        for (int half = 0; half < 2; half++) {
            const int m = m0 + wm + fm * 16 + g + half * 8;
            const int bb = m >> 11;
            const int s  = m & 2047;
            float* orow = Out + (((size_t)(bb * NHEADS + head)) * SEQ + s) * DHEAD;
#pragma unroll
            for (int fn = 0; fn < 4; fn++) {
                const int col = wn + fn * 8 + 2 * tg;
                float2 v;
                v.x = acc[fm][fn][2 * half]     + bias[col];
                v.y = acc[fm][fn][2 * half + 1] + bias[col + 1];
                *(float2*)(orow + col) = v;
            }
        }
    }
}

// ---------------------------------------------------------------------------
// Kernel 3: output projection via mma.sync.  Grid (32, 16).
// ---------------------------------------------------------------------------
__global__ void __launch_bounds__(256, 1) proj_gemm(
    const float* __restrict__ bO, float* __restrict__ out)
{
    extern __shared__ float smem[];
    const int m0 = blockIdx.x * 128;
    const int n0 = blockIdx.y * 128;

    const float* A  = g_Z + (size_t)m0 * DMODEL;
    const float* BT = g_WOT + (size_t)n0 * DMODEL;

    float acc[4][4][4];
    gemm_mainloop_mma(A, BT, smem, acc);

    const int tid  = threadIdx.x;
    const int wid  = tid >> 5, lane = tid & 31;
    const int wm   = (wid >> 2) * 64;
    const int wn   = (wid & 3) * 32;
    const int g    = lane >> 2;
    const int tg   = lane & 3;

#pragma unroll
    for (int fm = 0; fm < 4; fm++) {
#pragma unroll
        for (int half = 0; half < 2; half++) {
            const int m = m0 + wm + fm * 16 + g + half * 8;
            float* orow = out + (size_t)m * DMODEL + n0;
#pragma unroll
            for (int fn = 0; fn < 4; fn++) {
                const int col = wn + fn * 8 + 2 * tg;
                float2 v;
                v.x = acc[fm][fn][2 * half]     + bO[n0 + col];
                v.y = acc[fm][fn][2 * half + 1] + bO[n0 + col + 1];
                *(float2*)(orow + col) = v;
            }
        }
    }
}

// ---------------------------------------------------------------------------
// Batched transpose: in [z][R][C] -> out [z][C][R]
// ---------------------------------------------------------------------------
__global__ void __launch_bounds__(256) transpose_w(
    const float* __restrict__ in, float* __restrict__ out, int R, int C)
{
    __shared__ float t[32][33];
    const size_t zo = (size_t)blockIdx.z * R * C;
    in  += zo;
    out += zo;
    const int r0 = blockIdx.x * 32, c0 = blockIdx.y * 32;
#pragma unroll
    for (int i = threadIdx.y; i < 32; i += 8)
        t[i][threadIdx.x] = in[(size_t)(r0 + i) * C + c0 + threadIdx.x];
    __syncthreads();
#pragma unroll
    for (int i = threadIdx.y; i < 32; i += 8)
        out[(size_t)(c0 + i) * R + r0 + threadIdx.x] = t[threadIdx.x][i];
}

// ---------------------------------------------------------------------------
// Kernel 2: causal flash attention on tensor cores (tf32 mma.sync).
// Grid: (16, 32).  256 threads = 8 warps, warp w owns q rows [w*16, w*16+16).
// BM=128 q rows per CTA, BN=64 keys per iteration.
// Pads: Q/K 132, V 136, P 68 -> all fragment LDS bank-conflict-free.
// ---------------------------------------------------------------------------
#define AQPAD 132
#define AKPAD 132
#define AVPAD 136
#define APPAD 68
#define ATTN2_SMEM ((128 * AQPAD + 64 * AKPAD + 64 * AVPAD + 128 * APPAD) * 4)  // 171008

__global__ void __launch_bounds__(256, 1) attn_mma_kernel()
{
    extern __shared__ float sm[];
    float* Qs = sm;                          // [128][132]
    float* Ks = Qs + 128 * AQPAD;            // [64][132]
    float* Vs = Ks + 64 * AKPAD;             // [64][136]  (row = s, col = d)
    float* Ps = Vs + 64 * AVPAD;             // [128][68]

    const int bh = blockIdx.y;
    const int qb = (int)gridDim.x - 1 - (int)blockIdx.x;   // heavy blocks first
    const int tid = threadIdx.x, wid = tid >> 5, lane = tid & 31;
    const int g = lane >> 2, tg = lane & 3;
    const int wm = wid * 16;

    const float* Qbase = g_Q + (size_t)bh * SEQ * DHEAD + (size_t)qb * 128 * DHEAD;
    const float* Kbase = g_K + (size_t)bh * SEQ * DHEAD;
    const float* Vbase = g_V + (size_t)bh * SEQ * DHEAD;
    const float scale = 0.08838834764831845f;

    // Load Q tile (128x128), pre-scaled
    for (int i = tid; i < 128 * 32; i += 256) {
        const int row = i >> 5, c4 = (i & 31) << 2;
        float4 v = *(const float4*)(Qbase + (row << 7) + c4);
        v.x *= scale; v.y *= scale; v.z *= scale; v.w *= scale;
        *(float4*)&Qs[row * AQPAD + c4] = v;
    }

    const uint32_t sK = smem_u32(Ks);
    const uint32_t sV = smem_u32(Vs);

    float o[16][4];
#pragma unroll
    for (int nf = 0; nf < 16; nf++)
#pragma unroll
        for (int i = 0; i < 4; i++) o[nf][i] = 0.f;
    float mi0 = -1e30f, mi1 = -1e30f, li0 = 0.f, li1 = 0.f;

    const int row0 = qb * 128 + wm + g;      // global q row for this thread's low half
    const float* qrow0 = Qs + (wm + g) * AQPAD;
    const float* qrow1 = qrow0 + 8 * AQPAD;
    float* prow0 = Ps + (wm + g) * APPAD;
    float* prow1 = prow0 + 8 * APPAD;

    const int nkb = 2 * (qb + 1);
    for (int kb = 0; kb < nkb; kb++) {
        // Load K,V tiles (64x128) via cp.async
        for (int i = tid; i < 64 * 32; i += 256) {
            const int row = i >> 5, c4 = (i & 31) << 2;
            const int go = ((kb * 64 + row) << 7) + c4;
            CP_ASYNC16(sK + (uint32_t)((row * AKPAD + c4) * 4), Kbase + go);
            CP_ASYNC16(sV + (uint32_t)((row * AVPAD + c4) * 4), Vbase + go);
        }
        CP_COMMIT;
        CP_WAIT0;
        __syncthreads();

        // ---- S = Q @ K^T ----
        float sacc[8][4];
#pragma unroll
        for (int nf = 0; nf < 8; nf++)
#pragma unroll
            for (int i = 0; i < 4; i++) sacc[nf][i] = 0.f;

#pragma unroll
        for (int kk = 0; kk < 16; kk++) {
            uint32_t af[4];
            af[0] = f2tf(qrow0[kk * 8 + tg]);
            af[1] = f2tf(qrow1[kk * 8 + tg]);
            af[2] = f2tf(qrow0[kk * 8 + tg + 4]);
            af[3] = f2tf(qrow1[kk * 8 + tg + 4]);
#pragma unroll
            for (int nf = 0; nf < 8; nf++) {
                uint32_t bf[2];
                const float* krow = Ks + (nf * 8 + g) * AKPAD + kk * 8;
                bf[0] = f2tf(krow[tg]);
                bf[1] = f2tf(krow[tg + 4]);
                mma_m16n8k8_tf32(sacc[nf], af, bf);
            }
        }

        // ---- mask + online softmax ----
        float mx0 = -1e30f, mx1 = -1e30f;
#pragma unroll
        for (int nf = 0; nf < 8; nf++) {
            const int colb = kb * 64 + nf * 8 + 2 * tg;
            if (colb     > row0)     sacc[nf][0] = -1e30f;
            if (colb + 1 > row0)     sacc[nf][1] = -1e30f;
            if (colb     > row0 + 8) sacc[nf][2] = -1e30f;
            if (colb + 1 > row0 + 8) sacc[nf][3] = -1e30f;
            mx0 = fmaxf(mx0, fmaxf(sacc[nf][0], sacc[nf][1]));
            mx1 = fmaxf(mx1, fmaxf(sacc[nf][2], sacc[nf][3]));
        }
        mx0 = fmaxf(mx0, __shfl_xor_sync(0xffffffffu, mx0, 1));
        mx0 = fmaxf(mx0, __shfl_xor_sync(0xffffffffu, mx0, 2));
        mx1 = fmaxf(mx1, __shfl_xor_sync(0xffffffffu, mx1, 1));
        mx1 = fmaxf(mx1, __shfl_xor_sync(0xffffffffu, mx1, 2));

        const float mn0 = fmaxf(mi0, mx0), mn1 = fmaxf(mi1, mx1);
        const float f0 = __expf(mi0 - mn0), f1 = __expf(mi1 - mn1);
        float s0 = 0.f, s1 = 0.f;
#pragma unroll
        for (int nf = 0; nf < 8; nf++) {
            sacc[nf][0] = __expf(sacc[nf][0] - mn0);
            sacc[nf][1] = __expf(sacc[nf][1] - mn0);
            sacc[nf][2] = __expf(sacc[nf][2] - mn1);
            sacc[nf][3] = __expf(sacc[nf][3] - mn1);
            s0 += sacc[nf][0] + sacc[nf][1];
            s1 += sacc[nf][2] + sacc[nf][3];
        }
        s0 += __shfl_xor_sync(0xffffffffu, s0, 1);
        s0 += __shfl_xor_sync(0xffffffffu, s0, 2);
        s1 += __shfl_xor_sync(0xffffffffu, s1, 1);
        s1 += __shfl_xor_sync(0xffffffffu, s1, 2);
        li0 = li0 * f0 + s0;  li1 = li1 * f1 + s1;
        mi0 = mn0;            mi1 = mn1;

#pragma unroll
        for (int nf = 0; nf < 16; nf++) {
            o[nf][0] *= f0;  o[nf][1] *= f0;
            o[nf][2] *= f1;  o[nf][3] *= f1;
        }

        // stash P (each warp writes/reads only its own 16 rows)
#pragma unroll
        for (int nf = 0; nf < 8; nf++) {
            *(float2*)&prow0[nf * 8 + 2 * tg] = make_float2(sacc[nf][0], sacc[nf][1]);
            *(float2*)&prow1[nf * 8 + 2 * tg] = make_float2(sacc[nf][2], sacc[nf][3]);
        }
        __syncwarp();

        // ---- O += P @ V ----
#pragma unroll
        for (int ks = 0; ks < 8; ks++) {
            uint32_t af[4];
            af[0] = f2tf(prow0[ks * 8 + tg]);
            af[1] = f2tf(prow1[ks * 8 + tg]);
            af[2] = f2tf(prow0[ks * 8 + tg + 4]);
            af[3] = f2tf(prow1[ks * 8 + tg + 4]);
#pragma unroll
            for (int nf = 0; nf < 16; nf++) {
                uint32_t bf[2];
                bf[0] = f2tf(Vs[(ks * 8 + tg) * AVPAD + nf * 8 + g]);
                bf[1] = f2tf(Vs[(ks * 8 + tg + 4) * AVPAD + nf * 8 + g]);
                mma_m16n8k8_tf32(o[nf], af, bf);
            }
        }
        __syncthreads();
    }

    // ---- normalize + write to g_Z ----
    const float inv0 = 1.f / li0, inv1 = 1.f / li1;
    const int b    = bh >> 4;
    const int head = bh & 15;
    float* z0 = g_Z + ((size_t)(b * SEQ + row0)) * DMODEL + head * DHEAD;
    float* z1 = z0 + (size_t)8 * DMODEL;
#pragma unroll
    for (int nf = 0; nf < 16; nf++) {
        *(float2*)&z0[nf * 8 + 2 * tg] = make_float2(o[nf][0] * inv0, o[nf][1] * inv0);
        *(float2*)&z1[nf * 8 + 2 * tg] = make_float2(o[nf][2] * inv1, o[nf][3] * inv1);
    }
}

// ---------------------------------------------------------------------------
extern "C" void kernel_launch(void* const* d_in, const int* in_sizes, int n_in,
                              void* d_out, int out_size)
{
    const float* X  = (const float*)d_in[0];
    const float* WQ = (const float*)d_in[1];
    const float* bQ = (const float*)d_in[2];
    const float* WK = (const float*)d_in[3];
    const float* bK = (const float*)d_in[4];
    const float* WV = (const float*)d_in[5];
    const float* bV = (const float*)d_in[6];
    const float* WO = (const float*)d_in[7];
    const float* bO = (const float*)d_in[8];
    float* out = (float*)d_out;

    cudaFuncSetAttribute(qkv_gemm, cudaFuncAttributeMaxDynamicSharedMemorySize, GEMM_SMEM);
    cudaFuncSetAttribute(proj_gemm, cudaFuncAttributeMaxDynamicSharedMemorySize, GEMM_SMEM);
    cudaFuncSetAttribute(attn_mma_kernel, cudaFuncAttributeMaxDynamicSharedMemorySize, ATTN2_SMEM);

    float *wt = nullptr, *wot = nullptr;
    cudaGetSymbolAddress((void**)&wt, g_WT);
    cudaGetSymbolAddress((void**)&wot, g_WOT);

    transpose_w<<<dim3(64, 4, 16), dim3(32, 8)>>>(WQ, wt, DMODEL, DHEAD);
    transpose_w<<<dim3(64, 4, 16), dim3(32, 8)>>>(WK, wt + (size_t)16 * DHEAD * DMODEL, DMODEL, DHEAD);
    transpose_w<<<dim3(64, 4, 16), dim3(32, 8)>>>(WV, wt + (size_t)32 * DHEAD * DMODEL, DMODEL, DHEAD);
    transpose_w<<<dim3(64, 64, 1), dim3(32, 8)>>>(WO, wot, DMODEL, DMODEL);

    qkv_gemm<<<dim3(32, 48), 256, GEMM_SMEM>>>(X, bQ, bK, bV);
    attn_mma_kernel<<<dim3(16, 32), 256, ATTN2_SMEM>>>();
    proj_gemm<<<dim3(32, 16), 256, GEMM_SMEM>>>(bO, out);
}